// round 2
// baseline (speedup 1.0000x reference)
#include <cuda_runtime.h>

#define N_NODES   100000
#define N_EDGES   1200000
#define F         64
#define N_CLASSES 40

// ---------------- scratch (static device globals; no runtime alloc) ----------
__device__ int   g_src[N_EDGES];
__device__ int   g_dst[N_EDGES];
__device__ float g_dinv[N_NODES];                 // deg, then dinv in place
__device__ float g_buf[5][(size_t)N_NODES * F];   // 5 x 25.6MB feature buffers
__device__ int   g_is64;                          // edge dtype flag

// ---------------- dtype detection --------------------------------------------
// int64 little-endian nonneg < 2^31  => all odd 32-bit words are zero.
// int32 random node ids              => odd words are ids (virtually never all 0).
__global__ void k_detect(const unsigned* __restrict__ w) {
    __shared__ int any;
    if (threadIdx.x == 0) any = 0;
    __syncthreads();
    unsigned v = 0;
    for (int t = threadIdx.x; t < 4096; t += blockDim.x) v |= w[2 * t + 1];
    if (v) atomicOr(&any, 1);
    __syncthreads();
    if (threadIdx.x == 0) g_is64 = any ? 0 : 1;
}

// ---------------- small utility kernels --------------------------------------
__global__ void k_zero_deg() {
    int i = blockIdx.x * blockDim.x + threadIdx.x;
    if (i < N_NODES) g_dinv[i] = 0.f;
}

__global__ void k_zero_buf(int idx) {
    int i = blockIdx.x * blockDim.x + threadIdx.x;
    if (i < N_NODES * F) g_buf[idx][i] = 0.f;
}

// convert edges -> int32 (either dtype) and accumulate in-degree
__global__ void k_prep(const void* __restrict__ ei_raw) {
    int e = blockIdx.x * blockDim.x + threadIdx.x;
    if (e >= N_EDGES) return;
    int s, d;
    if (g_is64) {
        const long long* ei = (const long long*)ei_raw;
        s = (int)ei[e];
        d = (int)ei[(size_t)N_EDGES + e];
    } else {
        const int* ei = (const int*)ei_raw;
        s = ei[e];
        d = ei[N_EDGES + e];
    }
    // defensive clamp: never crash on unexpected data
    s = min(max(s, 0), N_NODES - 1);
    d = min(max(d, 0), N_NODES - 1);
    g_src[e] = s;
    g_dst[e] = d;
    atomicAdd(&g_dinv[d], 1.0f);
}

__global__ void k_dinv() {
    int i = blockIdx.x * blockDim.x + threadIdx.x;
    if (i < N_NODES) {
        float dg = g_dinv[i];
        g_dinv[i] = (dg > 0.f) ? rsqrtf(fmaxf(dg, 1.f)) : 0.f;
    }
}

// ---------------- SpMM: one warp per edge, float2 per lane --------------------
// out[dst] += dinv[src]*dinv[dst] * in[src]   (out must be pre-zeroed)
__global__ void k_spmm(const float* __restrict__ in_ext, int in_idx, int out_idx) {
    const float* __restrict__ in = in_ext ? in_ext : g_buf[in_idx];
    float* __restrict__ out = g_buf[out_idx];

    int gid  = blockIdx.x * blockDim.x + threadIdx.x;
    int e    = gid >> 5;
    int lane = gid & 31;
    if (e >= N_EDGES) return;

    int s = g_src[e];
    int d = g_dst[e];
    float w = g_dinv[s] * g_dinv[d];

    float2 v = ((const float2*)(in + (size_t)s * F))[lane];
    float* o = out + (size_t)d * F + 2 * lane;
    atomicAdd(o,     v.x * w);
    atomicAdd(o + 1, v.y * w);
}

// ---------------- TAG GEMM: out = relu(concat(h0..h3) @ W + b) ----------------
// Tile: 64 nodes x 64 cols per block, 128 threads, 8x4 microtile per thread.
#define XS_STRIDE 68
__global__ void __launch_bounds__(128)
k_gemm_tag(const float* __restrict__ h0_ext, int i0, int i1, int i2, int i3,
           const float* __restrict__ W, const float* __restrict__ b,
           int out_idx, int do_relu)
{
    __shared__ float Ws[64 * 64];
    __shared__ float Xs[64 * XS_STRIDE];

    const float* hops[4];
    hops[0] = h0_ext ? h0_ext : g_buf[i0];
    hops[1] = g_buf[i1];
    hops[2] = g_buf[i2];
    hops[3] = g_buf[i3];
    float* __restrict__ out = g_buf[out_idx];

    int tid = threadIdx.x;
    int tc  = (tid & 15) << 2;   // col base (0..60)
    int tn  = (tid >> 4) << 3;   // node base within tile (0..56)
    int nbase = blockIdx.x << 6;
    int nrem  = N_NODES - nbase;

    float acc[8][4];
#pragma unroll
    for (int r = 0; r < 8; ++r)
#pragma unroll
        for (int c = 0; c < 4; ++c) acc[r][c] = 0.f;

    for (int h = 0; h < 4; ++h) {
        const float* __restrict__ X  = hops[h];
        const float* __restrict__ Wh = W + h * 64 * 64;

        // load W chunk (row-major 64x64), coalesced
#pragma unroll
        for (int t = 0; t < 32; ++t) {
            int idx = tid + t * 128;
            Ws[idx] = Wh[idx];
        }
        // load X tile transposed: Xs[i][n]
#pragma unroll
        for (int t = 0; t < 32; ++t) {
            int idx = tid + t * 128;
            int n = idx >> 6, i = idx & 63;
            float v = (n < nrem) ? X[(size_t)(nbase + n) * F + i] : 0.f;
            Xs[i * XS_STRIDE + n] = v;
        }
        __syncthreads();

#pragma unroll 8
        for (int i = 0; i < 64; ++i) {
            float4 w4 = *(const float4*)&Ws[i * 64 + tc];
            float4 a0 = *(const float4*)&Xs[i * XS_STRIDE + tn];
            float4 a1 = *(const float4*)&Xs[i * XS_STRIDE + tn + 4];
            float a[8] = {a0.x, a0.y, a0.z, a0.w, a1.x, a1.y, a1.z, a1.w};
            float w[4] = {w4.x, w4.y, w4.z, w4.w};
#pragma unroll
            for (int r = 0; r < 8; ++r)
#pragma unroll
                for (int c = 0; c < 4; ++c)
                    acc[r][c] = fmaf(a[r], w[c], acc[r][c]);
        }
        __syncthreads();
    }

    float bv0 = b[tc], bv1 = b[tc + 1], bv2 = b[tc + 2], bv3 = b[tc + 3];
#pragma unroll
    for (int r = 0; r < 8; ++r) {
        int gn = nbase + tn + r;
        if (gn < N_NODES) {
            float4 o;
            o.x = acc[r][0] + bv0;
            o.y = acc[r][1] + bv1;
            o.z = acc[r][2] + bv2;
            o.w = acc[r][3] + bv3;
            if (do_relu) {
                o.x = fmaxf(o.x, 0.f); o.y = fmaxf(o.y, 0.f);
                o.z = fmaxf(o.z, 0.f); o.w = fmaxf(o.w, 0.f);
            }
            *(float4*)&out[(size_t)gn * F + tc] = o;
        }
    }
}

// ---------------- classifier: out = h @ Wc + bc  (64 -> 40) -------------------
// 128 threads/block, tile 128 nodes. Thread handles 4 nodes x 10 cols.
#define XT_STRIDE 132
__global__ void __launch_bounds__(128)
k_cls(int in_idx, const float* __restrict__ Wc, const float* __restrict__ bc,
      float* __restrict__ out)
{
    __shared__ float Ws[F * N_CLASSES];     // Ws[i*40 + c]
    __shared__ float XsT[F * XT_STRIDE];    // XsT[i][n], n in [0,128)

    const float* __restrict__ X = g_buf[in_idx];
    int tid = threadIdx.x;
    int nbase = blockIdx.x << 7;
    int nrem  = N_NODES - nbase;

    for (int idx = tid; idx < F * N_CLASSES; idx += 128)
        Ws[idx] = Wc[idx];

#pragma unroll
    for (int t = 0; t < 64; ++t) {
        int idx = tid + t * 128;
        int n = idx >> 6, i = idx & 63;
        float v = (n < nrem) ? X[(size_t)(nbase + n) * F + i] : 0.f;
        XsT[i * XT_STRIDE + n] = v;
    }
    __syncthreads();

    int n0 = (tid & 31) << 2;      // 4 consecutive nodes
    int c0 = (tid >> 5) * 10;      // 10 cols (uniform within warp)

    float acc[4][10];
#pragma unroll
    for (int r = 0; r < 4; ++r)
#pragma unroll
        for (int c = 0; c < 10; ++c) acc[r][c] = 0.f;

#pragma unroll 4
    for (int i = 0; i < F; ++i) {
        float4 a = *(const float4*)&XsT[i * XT_STRIDE + n0];
        float av[4] = {a.x, a.y, a.z, a.w};
#pragma unroll
        for (int c = 0; c < 10; ++c) {
            float w = Ws[i * N_CLASSES + c0 + c];   // broadcast within warp
#pragma unroll
            for (int r = 0; r < 4; ++r)
                acc[r][c] = fmaf(av[r], w, acc[r][c]);
        }
    }

#pragma unroll
    for (int r = 0; r < 4; ++r) {
        int gn = nbase + n0 + r;
        if (gn < N_NODES) {
#pragma unroll
            for (int c = 0; c < 10; ++c)
                out[(size_t)gn * N_CLASSES + c0 + c] = acc[r][c] + bc[c0 + c];
        }
    }
}

// ---------------- launch ------------------------------------------------------
extern "C" void kernel_launch(void* const* d_in, const int* in_sizes, int n_in,
                              void* d_out, int out_size)
{
    const float* x  = (const float*)d_in[0];
    const void*  ei = d_in[1];
    const float* W1 = (const float*)d_in[2];
    const float* b1 = (const float*)d_in[3];
    const float* W2 = (const float*)d_in[4];
    const float* b2 = (const float*)d_in[5];
    const float* Wc = (const float*)d_in[6];
    const float* bc = (const float*)d_in[7];
    float* out = (float*)d_out;

    const int ZB  = 256;
    const int nzN = (N_NODES + ZB - 1) / ZB;
    const int nzB = (N_NODES * F + ZB - 1) / ZB;
    const int neB = (N_EDGES + ZB - 1) / ZB;
    const int spmm_blocks = (N_EDGES * 32 + ZB - 1) / ZB;
    const int gemm_blocks = (N_NODES + 63) / 64;
    const int cls_blocks  = (N_NODES + 127) / 128;

    // dtype detect + degree + norm
    k_detect<<<1, 256>>>((const unsigned*)ei);
    k_zero_deg<<<nzN, ZB>>>();
    k_prep<<<neB, ZB>>>(ei);
    k_dinv<<<nzN, ZB>>>();

    // ---- layer 1: hops into buf0..buf2, h1 -> buf3 ----
    k_zero_buf<<<nzB, ZB>>>(0);
    k_spmm<<<spmm_blocks, ZB>>>(x, -1, 0);
    k_zero_buf<<<nzB, ZB>>>(1);
    k_spmm<<<spmm_blocks, ZB>>>(nullptr, 0, 1);
    k_zero_buf<<<nzB, ZB>>>(2);
    k_spmm<<<spmm_blocks, ZB>>>(nullptr, 1, 2);
    k_gemm_tag<<<gemm_blocks, 128>>>(x, -1, 0, 1, 2, W1, b1, 3, 1);

    // ---- layer 2: hops from buf3 into buf0..buf2, h2 -> buf4 ----
    k_zero_buf<<<nzB, ZB>>>(0);
    k_spmm<<<spmm_blocks, ZB>>>(nullptr, 3, 0);
    k_zero_buf<<<nzB, ZB>>>(1);
    k_spmm<<<spmm_blocks, ZB>>>(nullptr, 0, 1);
    k_zero_buf<<<nzB, ZB>>>(2);
    k_spmm<<<spmm_blocks, ZB>>>(nullptr, 1, 2);
    k_gemm_tag<<<gemm_blocks, 128>>>(nullptr, 3, 0, 1, 2, W2, b2, 4, 1);

    // ---- classifier ----
    k_cls<<<cls_blocks, 128>>>(4, Wc, bc, out);
}

// round 15
// speedup vs baseline: 1.7410x; 1.7410x over previous
#include <cuda_runtime.h>

#define N_NODES   100000
#define N_EDGES   1200000
#define F         64
#define N_CLASSES 40

#define SCAN_B    256
#define N_SCAN_BLOCKS ((N_NODES + SCAN_B - 1) / SCAN_B)   // 391

// ---------------- scratch (static device globals; no runtime alloc) ----------
__device__ int   g_deg[N_NODES];
__device__ int   g_rowptr[N_NODES + 1];
__device__ int   g_cursor[N_NODES];
__device__ int   g_bsum[N_SCAN_BLOCKS];
__device__ int   g_tmp_incl[N_NODES];
__device__ float g_dinv[N_NODES];
__device__ int2  g_csre[N_EDGES];                 // (src, bitcast weight)
__device__ float g_buf[5][(size_t)N_NODES * F];   // 5 x 25.6MB feature buffers
__device__ int   g_is64;                          // edge dtype flag

// ---------------- dtype detection --------------------------------------------
__global__ void k_detect(const unsigned* __restrict__ w) {
    __shared__ int any;
    if (threadIdx.x == 0) any = 0;
    __syncthreads();
    unsigned v = 0;
    for (int t = threadIdx.x; t < 4096; t += blockDim.x) v |= w[2 * t + 1];
    if (v) atomicOr(&any, 1);
    __syncthreads();
    if (threadIdx.x == 0) g_is64 = any ? 0 : 1;
}

__global__ void k_zero_deg() {
    int i = blockIdx.x * blockDim.x + threadIdx.x;
    if (i < N_NODES) g_deg[i] = 0;
}

// degree histogram (handles either edge dtype)
__global__ void k_hist(const void* __restrict__ ei_raw) {
    int e = blockIdx.x * blockDim.x + threadIdx.x;
    if (e >= N_EDGES) return;
    int d;
    if (g_is64) d = (int)((const long long*)ei_raw)[(size_t)N_EDGES + e];
    else        d = ((const int*)ei_raw)[N_EDGES + e];
    d = min(max(d, 0), N_NODES - 1);
    atomicAdd(&g_deg[d], 1);
}

__global__ void k_dinv() {
    int i = blockIdx.x * blockDim.x + threadIdx.x;
    if (i < N_NODES) {
        float dg = (float)g_deg[i];
        g_dinv[i] = (dg > 0.f) ? rsqrtf(dg) : 0.f;
    }
}

// ---------------- exclusive scan of degrees -> rowptr -------------------------
__global__ void k_scan1() {
    __shared__ int s[SCAN_B];
    int i = blockIdx.x * SCAN_B + threadIdx.x;
    int v = (i < N_NODES) ? g_deg[i] : 0;
    s[threadIdx.x] = v;
    __syncthreads();
#pragma unroll
    for (int off = 1; off < SCAN_B; off <<= 1) {
        int t = (threadIdx.x >= off) ? s[threadIdx.x - off] : 0;
        __syncthreads();
        s[threadIdx.x] += t;
        __syncthreads();
    }
    if (i < N_NODES) g_tmp_incl[i] = s[threadIdx.x];
    if (threadIdx.x == SCAN_B - 1) g_bsum[blockIdx.x] = s[SCAN_B - 1];
}

__global__ void k_scan2() {
    __shared__ int s[512];
    int t = threadIdx.x;
    s[t] = (t < N_SCAN_BLOCKS) ? g_bsum[t] : 0;
    __syncthreads();
#pragma unroll
    for (int off = 1; off < 512; off <<= 1) {
        int v = (t >= off) ? s[t - off] : 0;
        __syncthreads();
        s[t] += v;
        __syncthreads();
    }
    if (t < N_SCAN_BLOCKS) g_bsum[t] = s[t];
}

__global__ void k_scan3() {
    int i = blockIdx.x * SCAN_B + threadIdx.x;
    if (i < N_NODES) {
        int b = blockIdx.x;
        int boff = (b > 0) ? g_bsum[b - 1] : 0;
        int excl = g_tmp_incl[i] - g_deg[i] + boff;
        g_rowptr[i] = excl;
        g_cursor[i] = excl;
    }
    if (i == 0) g_rowptr[N_NODES] = N_EDGES;
}

// ---------------- scatter edges into CSR (precompute weights) -----------------
__global__ void k_scatter(const void* __restrict__ ei_raw) {
    int e = blockIdx.x * blockDim.x + threadIdx.x;
    if (e >= N_EDGES) return;
    int s, d;
    if (g_is64) {
        const long long* ei = (const long long*)ei_raw;
        s = (int)ei[e];
        d = (int)ei[(size_t)N_EDGES + e];
    } else {
        const int* ei = (const int*)ei_raw;
        s = ei[e];
        d = ei[N_EDGES + e];
    }
    s = min(max(s, 0), N_NODES - 1);
    d = min(max(d, 0), N_NODES - 1);
    float w = g_dinv[s] * g_dinv[d];
    int pos = atomicAdd(&g_cursor[d], 1);
    g_csre[pos] = make_int2(s, __float_as_int(w));
}

// ---------------- CSR SpMM: one warp per dst node, gather only ----------------
__global__ void __launch_bounds__(256, 8)
k_spmm_csr(const float* __restrict__ in_ext, int in_idx, int out_idx) {
    const float* __restrict__ in = in_ext ? in_ext : g_buf[in_idx];
    float* __restrict__ out = g_buf[out_idx];

    int warp = (blockIdx.x * blockDim.x + threadIdx.x) >> 5;
    int lane = threadIdx.x & 31;
    if (warp >= N_NODES) return;

    int k  = __ldg(&g_rowptr[warp]);
    int k1 = __ldg(&g_rowptr[warp + 1]);

    float a0 = 0.f, a1 = 0.f;

    // 4-wide chunks for MLP
    for (; k + 4 <= k1; k += 4) {
        int2 e0 = __ldg(&g_csre[k]),     e1 = __ldg(&g_csre[k + 1]);
        int2 e2 = __ldg(&g_csre[k + 2]), e3 = __ldg(&g_csre[k + 3]);
        float2 v0 = __ldg(((const float2*)(in + (size_t)e0.x * F)) + lane);
        float2 v1 = __ldg(((const float2*)(in + (size_t)e1.x * F)) + lane);
        float2 v2 = __ldg(((const float2*)(in + (size_t)e2.x * F)) + lane);
        float2 v3 = __ldg(((const float2*)(in + (size_t)e3.x * F)) + lane);
        float w0 = __int_as_float(e0.y), w1 = __int_as_float(e1.y);
        float w2 = __int_as_float(e2.y), w3 = __int_as_float(e3.y);
        a0 = fmaf(v0.x, w0, a0); a1 = fmaf(v0.y, w0, a1);
        a0 = fmaf(v1.x, w1, a0); a1 = fmaf(v1.y, w1, a1);
        a0 = fmaf(v2.x, w2, a0); a1 = fmaf(v2.y, w2, a1);
        a0 = fmaf(v3.x, w3, a0); a1 = fmaf(v3.y, w3, a1);
    }
    for (; k < k1; ++k) {
        int2 e = __ldg(&g_csre[k]);
        float w = __int_as_float(e.y);
        float2 v = __ldg(((const float2*)(in + (size_t)e.x * F)) + lane);
        a0 = fmaf(v.x, w, a0); a1 = fmaf(v.y, w, a1);
    }

    ((float2*)(out + (size_t)warp * F))[lane] = make_float2(a0, a1);
}

// ---------------- TAG GEMM: out = relu(concat(h0..h3) @ W + b) ----------------
#define XS_STRIDE 68
__global__ void __launch_bounds__(128)
k_gemm_tag(const float* __restrict__ h0_ext, int i0, int i1, int i2, int i3,
           const float* __restrict__ W, const float* __restrict__ b,
           int out_idx, int do_relu)
{
    __shared__ float Ws[64 * 64];
    __shared__ float Xs[64 * XS_STRIDE];

    const float* hops[4];
    hops[0] = h0_ext ? h0_ext : g_buf[i0];
    hops[1] = g_buf[i1];
    hops[2] = g_buf[i2];
    hops[3] = g_buf[i3];
    float* __restrict__ out = g_buf[out_idx];

    int tid = threadIdx.x;
    int tc  = (tid & 15) << 2;
    int tn  = (tid >> 4) << 3;
    int nbase = blockIdx.x << 6;
    int nrem  = N_NODES - nbase;

    float acc[8][4];
#pragma unroll
    for (int r = 0; r < 8; ++r)
#pragma unroll
        for (int c = 0; c < 4; ++c) acc[r][c] = 0.f;

    for (int h = 0; h < 4; ++h) {
        const float* __restrict__ X  = hops[h];
        const float* __restrict__ Wh = W + h * 64 * 64;

#pragma unroll
        for (int t = 0; t < 32; ++t) {
            int idx = tid + t * 128;
            Ws[idx] = Wh[idx];
        }
#pragma unroll
        for (int t = 0; t < 32; ++t) {
            int idx = tid + t * 128;
            int n = idx >> 6, i = idx & 63;
            float v = (n < nrem) ? X[(size_t)(nbase + n) * F + i] : 0.f;
            Xs[i * XS_STRIDE + n] = v;
        }
        __syncthreads();

#pragma unroll 8
        for (int i = 0; i < 64; ++i) {
            float4 w4 = *(const float4*)&Ws[i * 64 + tc];
            float4 a0 = *(const float4*)&Xs[i * XS_STRIDE + tn];
            float4 a1 = *(const float4*)&Xs[i * XS_STRIDE + tn + 4];
            float a[8] = {a0.x, a0.y, a0.z, a0.w, a1.x, a1.y, a1.z, a1.w};
            float w[4] = {w4.x, w4.y, w4.z, w4.w};
#pragma unroll
            for (int r = 0; r < 8; ++r)
#pragma unroll
                for (int c = 0; c < 4; ++c)
                    acc[r][c] = fmaf(a[r], w[c], acc[r][c]);
        }
        __syncthreads();
    }

    float bv0 = b[tc], bv1 = b[tc + 1], bv2 = b[tc + 2], bv3 = b[tc + 3];
#pragma unroll
    for (int r = 0; r < 8; ++r) {
        int gn = nbase + tn + r;
        if (gn < N_NODES) {
            float4 o;
            o.x = acc[r][0] + bv0;
            o.y = acc[r][1] + bv1;
            o.z = acc[r][2] + bv2;
            o.w = acc[r][3] + bv3;
            if (do_relu) {
                o.x = fmaxf(o.x, 0.f); o.y = fmaxf(o.y, 0.f);
                o.z = fmaxf(o.z, 0.f); o.w = fmaxf(o.w, 0.f);
            }
            *(float4*)&out[(size_t)gn * F + tc] = o;
        }
    }
}

// ---------------- classifier: out = h @ Wc + bc  (64 -> 40) -------------------
#define XT_STRIDE 132
__global__ void __launch_bounds__(128)
k_cls(int in_idx, const float* __restrict__ Wc, const float* __restrict__ bc,
      float* __restrict__ out)
{
    __shared__ float Ws[F * N_CLASSES];
    __shared__ float XsT[F * XT_STRIDE];

    const float* __restrict__ X = g_buf[in_idx];
    int tid = threadIdx.x;
    int nbase = blockIdx.x << 7;
    int nrem  = N_NODES - nbase;

    for (int idx = tid; idx < F * N_CLASSES; idx += 128)
        Ws[idx] = Wc[idx];

#pragma unroll
    for (int t = 0; t < 64; ++t) {
        int idx = tid + t * 128;
        int n = idx >> 6, i = idx & 63;
        float v = (n < nrem) ? X[(size_t)(nbase + n) * F + i] : 0.f;
        XsT[i * XT_STRIDE + n] = v;
    }
    __syncthreads();

    int n0 = (tid & 31) << 2;
    int c0 = (tid >> 5) * 10;

    float acc[4][10];
#pragma unroll
    for (int r = 0; r < 4; ++r)
#pragma unroll
        for (int c = 0; c < 10; ++c) acc[r][c] = 0.f;

#pragma unroll 4
    for (int i = 0; i < F; ++i) {
        float4 a = *(const float4*)&XsT[i * XT_STRIDE + n0];
        float av[4] = {a.x, a.y, a.z, a.w};
#pragma unroll
        for (int c = 0; c < 10; ++c) {
            float w = Ws[i * N_CLASSES + c0 + c];
#pragma unroll
            for (int r = 0; r < 4; ++r)
                acc[r][c] = fmaf(av[r], w, acc[r][c]);
        }
    }

#pragma unroll
    for (int r = 0; r < 4; ++r) {
        int gn = nbase + n0 + r;
        if (gn < N_NODES) {
#pragma unroll
            for (int c = 0; c < 10; ++c)
                out[(size_t)gn * N_CLASSES + c0 + c] = acc[r][c] + bc[c0 + c];
        }
    }
}

// ---------------- launch ------------------------------------------------------
extern "C" void kernel_launch(void* const* d_in, const int* in_sizes, int n_in,
                              void* d_out, int out_size)
{
    const float* x  = (const float*)d_in[0];
    const void*  ei = d_in[1];
    const float* W1 = (const float*)d_in[2];
    const float* b1 = (const float*)d_in[3];
    const float* W2 = (const float*)d_in[4];
    const float* b2 = (const float*)d_in[5];
    const float* Wc = (const float*)d_in[6];
    const float* bc = (const float*)d_in[7];
    float* out = (float*)d_out;

    const int ZB  = 256;
    const int nzN = (N_NODES + ZB - 1) / ZB;
    const int neB = (N_EDGES + ZB - 1) / ZB;
    const int spmm_blocks = (int)(((size_t)N_NODES * 32 + ZB - 1) / ZB);
    const int gemm_blocks = (N_NODES + 63) / 64;
    const int cls_blocks  = (N_NODES + 127) / 128;

    // ---- CSR build (once per launch) ----
    k_detect<<<1, 256>>>((const unsigned*)ei);
    k_zero_deg<<<nzN, ZB>>>();
    k_hist<<<neB, ZB>>>(ei);
    k_dinv<<<nzN, ZB>>>();
    k_scan1<<<N_SCAN_BLOCKS, SCAN_B>>>();
    k_scan2<<<1, 512>>>();
    k_scan3<<<N_SCAN_BLOCKS, SCAN_B>>>();
    k_scatter<<<neB, ZB>>>(ei);

    // ---- layer 1: hops into buf0..buf2, h1 -> buf3 ----
    k_spmm_csr<<<spmm_blocks, ZB>>>(x, -1, 0);
    k_spmm_csr<<<spmm_blocks, ZB>>>(nullptr, 0, 1);
    k_spmm_csr<<<spmm_blocks, ZB>>>(nullptr, 1, 2);
    k_gemm_tag<<<gemm_blocks, 128>>>(x, -1, 0, 1, 2, W1, b1, 3, 1);

    // ---- layer 2: hops from buf3 into buf0..buf2, h2 -> buf4 ----
    k_spmm_csr<<<spmm_blocks, ZB>>>(nullptr, 3, 0);
    k_spmm_csr<<<spmm_blocks, ZB>>>(nullptr, 0, 1);
    k_spmm_csr<<<spmm_blocks, ZB>>>(nullptr, 1, 2);
    k_gemm_tag<<<gemm_blocks, 128>>>(nullptr, 3, 0, 1, 2, W2, b2, 4, 1);

    // ---- classifier ----
    k_cls<<<cls_blocks, 128>>>(4, Wc, bc, out);
}